// round 11
// baseline (speedup 1.0000x reference)
#include <cuda_runtime.h>
#include <cuda_bf16.h>
#include <cstddef>

#define NN   8192
#define TS   64
#define NOUT 128

// ---------------- scratch (device globals: no allocation allowed) ----------
__device__ float g_adj[(size_t)NN * NN];     // 256 MB
__device__ float g_H1[(size_t)NN * NOUT];
__device__ float g_U1[(size_t)NN * NOUT];
__device__ float g_H2[(size_t)NN * NOUT];

// ---------------- zero kernel ----------------------------------------------
__global__ void k_zero(float* __restrict__ p, int n) {
    int i = blockIdx.x * 256 + threadIdx.x;
    if (i < n) p[i] = 0.f;
}

// ---------------- pass 1: adj build + fused A@token -------------------------
// Grid (128,128); CTA handles unordered tile pair {I,J}, J>=I.
// Each thread owns 16 CONTIGUOUS columns -> 4 LDG.128 per path per side.
__global__ __launch_bounds__(256) void k_build(
    const float* __restrict__ A1, const float* __restrict__ A2, const float* __restrict__ A3,
    const float* __restrict__ T1, const float* __restrict__ T2, const float* __restrict__ T3,
    const float* __restrict__ wb, float* __restrict__ feat_out)
{
    int I = blockIdx.y, J = blockIdx.x;
    if (J < I) return;

    __shared__ float sT1[TS][68];   // stride 68 words: rows 272B (16B aligned)
    __shared__ float sT2[TS][68];
    __shared__ float tokJ[3][TS][10];
    __shared__ float tokI[3][TS][10];

    int tid = threadIdx.x;
    int Ig = I * TS, Jg = J * TS;
    const float* Aks[3] = {A1, A2, A3};
    const float* Tks[3] = {T1, T2, T3};
    float wk3[3] = {wb[0], wb[1], wb[2]};

    for (int idx = tid; idx < 3 * TS * 10; idx += 256) {
        int k = idx / (TS * 10);
        int rem = idx % (TS * 10);
        int row = rem / 10, t = rem % 10;
        tokJ[k][row][t] = Tks[k][(Jg + row) * 10 + t];
        tokI[k][row][t] = Tks[k][(Ig + row) * 10 + t];
    }
    __syncthreads();

    int r = tid >> 2;        // row within tile (0..63)
    int q = tid & 3;         // column quarter: cols 16q..16q+15
    bool diag = (I == J);

    // ---- side A: block (I,J) rows Ig+r, cols Jg+16q.. ----
    {
        float tval[16];
        #pragma unroll
        for (int i = 0; i < 16; i++) tval[i] = 0.f;
        #pragma unroll
        for (int k = 0; k < 3; k++) {
            const float4* rp = (const float4*)(Aks[k] + (size_t)(Ig + r) * NN + Jg + 16 * q);
            float wk = wk3[k];
            float ft[10];
            #pragma unroll
            for (int t = 0; t < 10; t++) ft[t] = 0.f;
            #pragma unroll
            for (int j = 0; j < 4; j++) {
                float4 a4 = rp[j];
                float aa[4] = {a4.x, a4.y, a4.z, a4.w};
                #pragma unroll
                for (int c = 0; c < 4; c++) {
                    int i = 4 * j + c;
                    float a = aa[c];
                    tval[i] += wk * a;
                    #pragma unroll
                    for (int t = 0; t < 10; t++) ft[t] += a * tokJ[k][16 * q + i][t];
                }
            }
            #pragma unroll
            for (int t = 0; t < 10; t++) {
                float v = ft[t];
                v += __shfl_down_sync(0xffffffffu, v, 2, 4);
                v += __shfl_down_sync(0xffffffffu, v, 1, 4);
                if (q == 0)
                    atomicAdd(&feat_out[(size_t)k * NN * 10 + (size_t)(Ig + r) * 10 + t], v);
            }
        }
        #pragma unroll
        for (int j = 0; j < 4; j++)
            *(float4*)&sT1[r][16 * q + 4 * j] =
                make_float4(tval[4 * j], tval[4 * j + 1], tval[4 * j + 2], tval[4 * j + 3]);
    }

    // ---- side B: block (J,I) rows Jg+r, cols Ig+16q.. (skip on diagonal) ----
    if (!diag) {
        float tval[16];
        #pragma unroll
        for (int i = 0; i < 16; i++) tval[i] = 0.f;
        #pragma unroll
        for (int k = 0; k < 3; k++) {
            const float4* rp = (const float4*)(Aks[k] + (size_t)(Jg + r) * NN + Ig + 16 * q);
            float wk = wk3[k];
            float ft[10];
            #pragma unroll
            for (int t = 0; t < 10; t++) ft[t] = 0.f;
            #pragma unroll
            for (int j = 0; j < 4; j++) {
                float4 a4 = rp[j];
                float aa[4] = {a4.x, a4.y, a4.z, a4.w};
                #pragma unroll
                for (int c = 0; c < 4; c++) {
                    int i = 4 * j + c;
                    float a = aa[c];
                    tval[i] += wk * a;
                    #pragma unroll
                    for (int t = 0; t < 10; t++) ft[t] += a * tokI[k][16 * q + i][t];
                }
            }
            #pragma unroll
            for (int t = 0; t < 10; t++) {
                float v = ft[t];
                v += __shfl_down_sync(0xffffffffu, v, 2, 4);
                v += __shfl_down_sync(0xffffffffu, v, 1, 4);
                if (q == 0)
                    atomicAdd(&feat_out[(size_t)k * NN * 10 + (size_t)(Jg + r) * 10 + t], v);
            }
        }
        #pragma unroll
        for (int j = 0; j < 4; j++)
            *(float4*)&sT2[r][16 * q + 4 * j] =
                make_float4(tval[4 * j], tval[4 * j + 1], tval[4 * j + 2], tval[4 * j + 3]);
    }
    __syncthreads();

    // ---- write adj tiles (coalesced rows; transposed via smem) ----
    int y = tid & 63, xb = tid >> 6;
    if (diag) {
        #pragma unroll
        for (int i = 0; i < 16; i++) {
            int x = xb + 4 * i;
            g_adj[(size_t)(Ig + x) * NN + Jg + y] = sT1[x][y] + sT1[y][x];
        }
    } else {
        #pragma unroll
        for (int i = 0; i < 16; i++) {
            int x = xb + 4 * i;
            g_adj[(size_t)(Ig + x) * NN + Jg + y] = sT1[x][y] + sT2[y][x];
            g_adj[(size_t)(Jg + x) * NN + Ig + y] = sT2[x][y] + sT1[y][x];
        }
    }
}

// ---------------- fp32 SGEMM: 64x64 tile, 128 threads, 4x8 microtile --------
// C[M x 128] = A[M x K] @ B[K x 128] (B row-major, ldb=128),
// optional +bias[col], optional C = 0.5*(C + comb).
// Grid: (M/64, 2). Double-buffered smem, BK=16, A staged transposed.
__device__ __forceinline__ void gemm_body(
    const float* __restrict__ A, int lda, int K,
    const float* __restrict__ B,
    const float* __restrict__ bias,
    const float* __restrict__ comb,
    float* __restrict__ C)
{
    __shared__ float sA[2][16][68];   // [k][m], row stride 272B (16B aligned)
    __shared__ float sB[2][16][68];   // [k][n]

    int t = threadIdx.x;
    int rowBase = blockIdx.x * 64;
    int cBase   = blockIdx.y * 64;

    float acc[4][8];
    #pragma unroll
    for (int i = 0; i < 4; i++)
        #pragma unroll
        for (int j = 0; j < 8; j++) acc[i][j] = 0.f;

    // A-load mapping: idx = t + 128*j -> (row = idx>>2, kq = (idx&3)*4)
    int a_row0 = t >> 2;
    int a_kq   = (t & 3) * 4;
    // B-load mapping: idx = t + 128*j -> (kk = idx>>4, n4 = idx&15)
    int b_k0 = t >> 4;          // 0..7 ; second j adds 8
    int b_n4 = (t & 15) * 4;

    // compute fragment mapping
    int tm = (t & 15) * 4;      // rows tm..tm+3
    int tn = (t >> 4) * 4;      // cols tn..tn+3 and tn+32..tn+35

    float4 ra[2], rb[2];

    // ---- preload tile 0 ----
    {
        const float* ap = A + (size_t)(rowBase + a_row0) * lda + a_kq;
        ra[0] = *(const float4*)(ap);
        ra[1] = *(const float4*)(ap + (size_t)32 * lda);
        const float* bp = B + (size_t)b_k0 * 128 + cBase + b_n4;
        rb[0] = *(const float4*)(bp);
        rb[1] = *(const float4*)(bp + 8 * 128);
    }
    {
        float aa0[4] = {ra[0].x, ra[0].y, ra[0].z, ra[0].w};
        float aa1[4] = {ra[1].x, ra[1].y, ra[1].z, ra[1].w};
        #pragma unroll
        for (int c = 0; c < 4; c++) {
            sA[0][a_kq + c][a_row0]      = aa0[c];
            sA[0][a_kq + c][a_row0 + 32] = aa1[c];
        }
        *(float4*)&sB[0][b_k0][b_n4]     = rb[0];
        *(float4*)&sB[0][b_k0 + 8][b_n4] = rb[1];
    }
    __syncthreads();

    int cur = 0;
    for (int k0 = 0; k0 < K; k0 += 16) {
        bool has_next = (k0 + 16 < K);
        if (has_next) {
            const float* ap = A + (size_t)(rowBase + a_row0) * lda + k0 + 16 + a_kq;
            ra[0] = *(const float4*)(ap);
            ra[1] = *(const float4*)(ap + (size_t)32 * lda);
            const float* bp = B + (size_t)(k0 + 16 + b_k0) * 128 + cBase + b_n4;
            rb[0] = *(const float4*)(bp);
            rb[1] = *(const float4*)(bp + 8 * 128);
        }

        #pragma unroll
        for (int kk = 0; kk < 16; kk++) {
            float4 av = *(const float4*)&sA[cur][kk][tm];
            float4 b0 = *(const float4*)&sB[cur][kk][tn];
            float4 b1 = *(const float4*)&sB[cur][kk][tn + 32];
            float a4[4] = {av.x, av.y, av.z, av.w};
            float bvv[8] = {b0.x, b0.y, b0.z, b0.w, b1.x, b1.y, b1.z, b1.w};
            #pragma unroll
            for (int i = 0; i < 4; i++)
                #pragma unroll
                for (int j = 0; j < 8; j++)
                    acc[i][j] += a4[i] * bvv[j];
        }

        if (has_next) {
            int nxt = cur ^ 1;
            float aa0[4] = {ra[0].x, ra[0].y, ra[0].z, ra[0].w};
            float aa1[4] = {ra[1].x, ra[1].y, ra[1].z, ra[1].w};
            #pragma unroll
            for (int c = 0; c < 4; c++) {
                sA[nxt][a_kq + c][a_row0]      = aa0[c];
                sA[nxt][a_kq + c][a_row0 + 32] = aa1[c];
            }
            *(float4*)&sB[nxt][b_k0][b_n4]     = rb[0];
            *(float4*)&sB[nxt][b_k0 + 8][b_n4] = rb[1];
            __syncthreads();
            cur = nxt;
        }
    }

    // ---- epilogue ----
    #pragma unroll
    for (int i = 0; i < 4; i++) {
        int row = rowBase + tm + i;
        #pragma unroll
        for (int ch = 0; ch < 2; ch++) {
            int col0 = cBase + tn + ch * 32;
            float vv[4];
            #pragma unroll
            for (int j = 0; j < 4; j++) {
                float x = acc[i][ch * 4 + j];
                if (bias) x += bias[col0 + j];
                if (comb) x = 0.5f * (x + comb[(size_t)row * 128 + col0 + j]);
                vv[j] = x;
            }
            *(float4*)(C + (size_t)row * 128 + col0) =
                make_float4(vv[0], vv[1], vv[2], vv[3]);
        }
    }
}

__global__ __launch_bounds__(128) void k_gemm_h1(const float* __restrict__ f,
                                                 const float* __restrict__ W1) {
    gemm_body(f, 256, 256, W1, nullptr, nullptr, g_H1);
}
__global__ __launch_bounds__(128) void k_gemm_u1(const float* __restrict__ b1) {
    gemm_body(g_adj, NN, NN, g_H1, b1, nullptr, g_U1);
}
__global__ __launch_bounds__(128) void k_gemm_h2(const float* __restrict__ W2) {
    gemm_body(g_U1, 128, 128, W2, nullptr, nullptr, g_H2);
}
__global__ __launch_bounds__(128) void k_gemm_out(const float* __restrict__ b2,
                                                  float* __restrict__ out) {
    gemm_body(g_adj, NN, NN, g_H2, b2, g_U1, out);
}

// ---------------- launch ----------------------------------------------------
extern "C" void kernel_launch(void* const* d_in, const int* in_sizes, int n_in,
                              void* d_out, int out_size) {
    const float* feature = (const float*)d_in[0];
    const float* A1 = (const float*)d_in[1];
    const float* A2 = (const float*)d_in[2];
    const float* A3 = (const float*)d_in[3];
    const float* T1 = (const float*)d_in[4];
    const float* T2 = (const float*)d_in[5];
    const float* T3 = (const float*)d_in[6];
    const float* wb = (const float*)d_in[7];
    const float* W1 = (const float*)d_in[8];
    const float* b1 = (const float*)d_in[9];
    const float* W2 = (const float*)d_in[10];
    const float* b2 = (const float*)d_in[11];

    float* out = (float*)d_out;                      // output: 8192*128
    float* feat_out = out + (size_t)NN * NOUT;       // A1f, A2f, A3f: 3 * 8192*10

    int nfeat = 3 * NN * 10;
    k_zero<<<(nfeat + 255) / 256, 256>>>(feat_out, nfeat);

    dim3 gb(128, 128);
    k_build<<<gb, 256>>>(A1, A2, A3, T1, T2, T3, wb, feat_out);

    dim3 gg(128, 2);
    k_gemm_h1<<<gg, 128>>>(feature, W1);
    k_gemm_u1<<<gg, 128>>>(b1);
    k_gemm_h2<<<gg, 128>>>(W2);
    k_gemm_out<<<gg, 128>>>(b2, out);
}

// round 12
// speedup vs baseline: 2.0460x; 2.0460x over previous
#include <cuda_runtime.h>
#include <cuda_bf16.h>
#include <cstddef>

#define NN   8192
#define TS   64
#define NOUT 128

// ---------------- scratch (device globals: no allocation allowed) ----------
__device__ float g_adj[(size_t)NN * NN];     // 256 MB
__device__ float g_H1[(size_t)NN * NOUT];
__device__ float g_U1[(size_t)NN * NOUT];
__device__ float g_H2[(size_t)NN * NOUT];

// ---------------- zero kernel ----------------------------------------------
__global__ void k_zero(float* __restrict__ p, int n) {
    int i = blockIdx.x * 256 + threadIdx.x;
    if (i < n) p[i] = 0.f;
}

// ---------------- pass 1: adj build + fused A@token (R9 version) ------------
// Grid (128,128); CTA handles unordered tile pair {I,J}, J>=I.
// Reads each A element exactly once; writes adj[I,J] and adj[J,I].
__global__ __launch_bounds__(256) void k_build(
    const float* __restrict__ A1, const float* __restrict__ A2, const float* __restrict__ A3,
    const float* __restrict__ T1, const float* __restrict__ T2, const float* __restrict__ T3,
    const float* __restrict__ wb, float* __restrict__ feat_out)
{
    int I = blockIdx.y, J = blockIdx.x;
    if (J < I) return;

    __shared__ float sT1[TS][TS + 1];
    __shared__ float sT2[TS][TS + 1];
    __shared__ float tokJ[3][TS][10];
    __shared__ float tokI[3][TS][10];

    int tid = threadIdx.x;
    int Ig = I * TS, Jg = J * TS;
    const float* Aks[3] = {A1, A2, A3};
    const float* Tks[3] = {T1, T2, T3};
    float wk3[3] = {wb[0], wb[1], wb[2]};

    for (int idx = tid; idx < 3 * TS * 10; idx += 256) {
        int k = idx / (TS * 10);
        int rem = idx % (TS * 10);
        int row = rem / 10, t = rem % 10;
        tokJ[k][row][t] = Tks[k][(Jg + row) * 10 + t];
        tokI[k][row][t] = Tks[k][(Ig + row) * 10 + t];
    }
    __syncthreads();

    int r = tid >> 2;        // row within tile (0..63)
    int q = tid & 3;         // column quadrant; thread handles cols q+4*yy
    bool diag = (I == J);

    // ---- side A: block (I,J) rows Ig+r, cols Jg+* ----
    {
        float tval[16];
        #pragma unroll
        for (int yy = 0; yy < 16; yy++) tval[yy] = 0.f;
        #pragma unroll
        for (int k = 0; k < 3; k++) {
            const float* rowp = Aks[k] + (size_t)(Ig + r) * NN + Jg + q;
            float wk = wk3[k];
            float ft[10];
            #pragma unroll
            for (int t = 0; t < 10; t++) ft[t] = 0.f;
            #pragma unroll
            for (int yy = 0; yy < 16; yy++) {
                int y = q + 4 * yy;
                float a = rowp[4 * yy];
                tval[yy] += wk * a;
                #pragma unroll
                for (int t = 0; t < 10; t++) ft[t] += a * tokJ[k][y][t];
            }
            #pragma unroll
            for (int t = 0; t < 10; t++) {
                float v = ft[t];
                v += __shfl_down_sync(0xffffffffu, v, 2, 4);
                v += __shfl_down_sync(0xffffffffu, v, 1, 4);
                if (q == 0)
                    atomicAdd(&feat_out[(size_t)k * NN * 10 + (size_t)(Ig + r) * 10 + t], v);
            }
        }
        #pragma unroll
        for (int yy = 0; yy < 16; yy++) sT1[r][q + 4 * yy] = tval[yy];
    }

    // ---- side B: block (J,I) rows Jg+r, cols Ig+* (skip on diagonal) ----
    if (!diag) {
        float tval[16];
        #pragma unroll
        for (int yy = 0; yy < 16; yy++) tval[yy] = 0.f;
        #pragma unroll
        for (int k = 0; k < 3; k++) {
            const float* rowp = Aks[k] + (size_t)(Jg + r) * NN + Ig + q;
            float wk = wk3[k];
            float ft[10];
            #pragma unroll
            for (int t = 0; t < 10; t++) ft[t] = 0.f;
            #pragma unroll
            for (int yy = 0; yy < 16; yy++) {
                int y = q + 4 * yy;
                float a = rowp[4 * yy];
                tval[yy] += wk * a;
                #pragma unroll
                for (int t = 0; t < 10; t++) ft[t] += a * tokI[k][y][t];
            }
            #pragma unroll
            for (int t = 0; t < 10; t++) {
                float v = ft[t];
                v += __shfl_down_sync(0xffffffffu, v, 2, 4);
                v += __shfl_down_sync(0xffffffffu, v, 1, 4);
                if (q == 0)
                    atomicAdd(&feat_out[(size_t)k * NN * 10 + (size_t)(Jg + r) * 10 + t], v);
            }
        }
        #pragma unroll
        for (int yy = 0; yy < 16; yy++) sT2[r][q + 4 * yy] = tval[yy];
    }
    __syncthreads();

    // ---- write adj tiles (coalesced; transposed reads via padded smem) ----
    int y = tid & 63, xb = tid >> 6;
    if (diag) {
        #pragma unroll
        for (int i = 0; i < 16; i++) {
            int x = xb + 4 * i;
            g_adj[(size_t)(Ig + x) * NN + Jg + y] = sT1[x][y] + sT1[y][x];
        }
    } else {
        #pragma unroll
        for (int i = 0; i < 16; i++) {
            int x = xb + 4 * i;
            g_adj[(size_t)(Ig + x) * NN + Jg + y] = sT1[x][y] + sT2[y][x];
            g_adj[(size_t)(Jg + x) * NN + Ig + y] = sT2[x][y] + sT1[y][x];
        }
    }
}

// ---------------- fp32 SGEMM: 64x64 tile, 256 threads, 4x4 microtile --------
// C[M x 128] = A[M x K] @ B[K x 128] (row-major, ldb=128),
// optional +bias[col], optional C = 0.5*(C + comb).
// Grid: (M/64, 2). Double-buffered smem (BK=16), A staged TRANSPOSED so the
// inner step is 2x LDS.128 + 16 FMA.
__device__ __forceinline__ void gemm_body(
    const float* __restrict__ A, int lda, int K,
    const float* __restrict__ B,
    const float* __restrict__ bias,
    const float* __restrict__ comb,
    float* __restrict__ C)
{
    __shared__ float sA[2][16][68];   // [buf][k][m], 16B-aligned rows
    __shared__ float sB[2][16][68];   // [buf][k][n]

    int t = threadIdx.x;
    int rowBase = blockIdx.x * 64;
    int cBase   = blockIdx.y * 64;

    float acc[4][4];
    #pragma unroll
    for (int i = 0; i < 4; i++)
        #pragma unroll
        for (int j = 0; j < 4; j++) acc[i][j] = 0.f;

    // A-tile load: 64 rows x 16 k = 1024 floats = 1 float4/thread
    int a_row = t >> 2;            // 0..63
    int a_k4  = (t & 3) * 4;       // 0,4,8,12
    // B-tile load: 16 k x 64 n = 1024 floats = 1 float4/thread
    int b_k  = t >> 4;             // 0..15
    int b_n4 = (t & 15) * 4;       // 0..60

    // compute fragment: 16x16 threads, 4x4 each
    int tm = (t & 15) * 4;         // rows tm..tm+3
    int tn = (t >> 4) * 4;         // cols tn..tn+3

    float4 ra, rb;

    // ---- preload tile 0 ----
    ra = *(const float4*)(A + (size_t)(rowBase + a_row) * lda + a_k4);
    rb = *(const float4*)(B + (size_t)b_k * 128 + cBase + b_n4);
    {
        float aa[4] = {ra.x, ra.y, ra.z, ra.w};
        #pragma unroll
        for (int c = 0; c < 4; c++) sA[0][a_k4 + c][a_row] = aa[c];
        *(float4*)&sB[0][b_k][b_n4] = rb;
    }
    __syncthreads();

    int cur = 0;
    for (int k0 = 0; k0 < K; k0 += 16) {
        bool has_next = (k0 + 16 < K);
        if (has_next) {
            ra = *(const float4*)(A + (size_t)(rowBase + a_row) * lda + k0 + 16 + a_k4);
            rb = *(const float4*)(B + (size_t)(k0 + 16 + b_k) * 128 + cBase + b_n4);
        }

        #pragma unroll
        for (int kk = 0; kk < 16; kk++) {
            float4 av = *(const float4*)&sA[cur][kk][tm];
            float4 bv = *(const float4*)&sB[cur][kk][tn];
            float a4[4] = {av.x, av.y, av.z, av.w};
            float b4[4] = {bv.x, bv.y, bv.z, bv.w};
            #pragma unroll
            for (int i = 0; i < 4; i++)
                #pragma unroll
                for (int j = 0; j < 4; j++)
                    acc[i][j] += a4[i] * b4[j];
        }

        if (has_next) {
            int nxt = cur ^ 1;
            float aa[4] = {ra.x, ra.y, ra.z, ra.w};
            #pragma unroll
            for (int c = 0; c < 4; c++) sA[nxt][a_k4 + c][a_row] = aa[c];
            *(float4*)&sB[nxt][b_k][b_n4] = rb;
            __syncthreads();
            cur = nxt;
        }
    }

    // ---- epilogue ----
    #pragma unroll
    for (int i = 0; i < 4; i++) {
        int row = rowBase + tm + i;
        int col0 = cBase + tn;
        float vv[4];
        #pragma unroll
        for (int j = 0; j < 4; j++) {
            float x = acc[i][j];
            if (bias) x += bias[col0 + j];
            if (comb) x = 0.5f * (x + comb[(size_t)row * 128 + col0 + j]);
            vv[j] = x;
        }
        *(float4*)(C + (size_t)row * 128 + col0) = make_float4(vv[0], vv[1], vv[2], vv[3]);
    }
}

__global__ __launch_bounds__(256) void k_gemm_h1(const float* __restrict__ f,
                                                 const float* __restrict__ W1) {
    gemm_body(f, 256, 256, W1, nullptr, nullptr, g_H1);
}
__global__ __launch_bounds__(256) void k_gemm_u1(const float* __restrict__ b1) {
    gemm_body(g_adj, NN, NN, g_H1, b1, nullptr, g_U1);
}
__global__ __launch_bounds__(256) void k_gemm_h2(const float* __restrict__ W2) {
    gemm_body(g_U1, 128, 128, W2, nullptr, nullptr, g_H2);
}
__global__ __launch_bounds__(256) void k_gemm_out(const float* __restrict__ b2,
                                                  float* __restrict__ out) {
    gemm_body(g_adj, NN, NN, g_H2, b2, g_U1, out);
}

// ---------------- launch ----------------------------------------------------
extern "C" void kernel_launch(void* const* d_in, const int* in_sizes, int n_in,
                              void* d_out, int out_size) {
    const float* feature = (const float*)d_in[0];
    const float* A1 = (const float*)d_in[1];
    const float* A2 = (const float*)d_in[2];
    const float* A3 = (const float*)d_in[3];
    const float* T1 = (const float*)d_in[4];
    const float* T2 = (const float*)d_in[5];
    const float* T3 = (const float*)d_in[6];
    const float* wb = (const float*)d_in[7];
    const float* W1 = (const float*)d_in[8];
    const float* b1 = (const float*)d_in[9];
    const float* W2 = (const float*)d_in[10];
    const float* b2 = (const float*)d_in[11];

    float* out = (float*)d_out;                      // output: 8192*128
    float* feat_out = out + (size_t)NN * NOUT;       // A1f, A2f, A3f: 3 * 8192*10

    int nfeat = 3 * NN * 10;
    k_zero<<<(nfeat + 255) / 256, 256>>>(feat_out, nfeat);

    dim3 gb(128, 128);
    k_build<<<gb, 256>>>(A1, A2, A3, T1, T2, T3, wb, feat_out);

    dim3 gg(128, 2);
    k_gemm_h1<<<gg, 256>>>(feature, W1);
    k_gemm_u1<<<gg, 256>>>(b1);
    k_gemm_h2<<<gg, 256>>>(W2);
    k_gemm_out<<<gg, 256>>>(b2, out);
}

// round 15
// speedup vs baseline: 2.5128x; 1.2281x over previous
#include <cuda_runtime.h>
#include <cuda_bf16.h>
#include <cstddef>

#define NN   8192
#define TS   64
#define NOUT 128

// ---------------- scratch (device globals: no allocation allowed) ----------
__device__ float g_adj[(size_t)NN * NN];     // 256 MB
__device__ float g_H1[(size_t)NN * NOUT];
__device__ float g_U1[(size_t)NN * NOUT];
__device__ float g_H2[(size_t)NN * NOUT];

// ---------------- zero kernel ----------------------------------------------
__global__ void k_zero(float* __restrict__ p, int n) {
    int i = blockIdx.x * 256 + threadIdx.x;
    if (i < n) p[i] = 0.f;
}

// ---------------- pass 1: adj build + fused A@token (unchanged) -------------
__global__ __launch_bounds__(256) void k_build(
    const float* __restrict__ A1, const float* __restrict__ A2, const float* __restrict__ A3,
    const float* __restrict__ T1, const float* __restrict__ T2, const float* __restrict__ T3,
    const float* __restrict__ wb, float* __restrict__ feat_out)
{
    int I = blockIdx.y, J = blockIdx.x;
    if (J < I) return;

    __shared__ float sT1[TS][TS + 1];
    __shared__ float sT2[TS][TS + 1];
    __shared__ float tokJ[3][TS][10];
    __shared__ float tokI[3][TS][10];

    int tid = threadIdx.x;
    int Ig = I * TS, Jg = J * TS;
    const float* Aks[3] = {A1, A2, A3};
    const float* Tks[3] = {T1, T2, T3};
    float wk3[3] = {wb[0], wb[1], wb[2]};

    for (int idx = tid; idx < 3 * TS * 10; idx += 256) {
        int k = idx / (TS * 10);
        int rem = idx % (TS * 10);
        int row = rem / 10, t = rem % 10;
        tokJ[k][row][t] = Tks[k][(Jg + row) * 10 + t];
        tokI[k][row][t] = Tks[k][(Ig + row) * 10 + t];
    }
    __syncthreads();

    int r = tid >> 2;
    int q = tid & 3;
    bool diag = (I == J);

    {
        float tval[16];
        #pragma unroll
        for (int yy = 0; yy < 16; yy++) tval[yy] = 0.f;
        #pragma unroll
        for (int k = 0; k < 3; k++) {
            const float* rowp = Aks[k] + (size_t)(Ig + r) * NN + Jg + q;
            float wk = wk3[k];
            float ft[10];
            #pragma unroll
            for (int t = 0; t < 10; t++) ft[t] = 0.f;
            #pragma unroll
            for (int yy = 0; yy < 16; yy++) {
                int y = q + 4 * yy;
                float a = rowp[4 * yy];
                tval[yy] += wk * a;
                #pragma unroll
                for (int t = 0; t < 10; t++) ft[t] += a * tokJ[k][y][t];
            }
            #pragma unroll
            for (int t = 0; t < 10; t++) {
                float v = ft[t];
                v += __shfl_down_sync(0xffffffffu, v, 2, 4);
                v += __shfl_down_sync(0xffffffffu, v, 1, 4);
                if (q == 0)
                    atomicAdd(&feat_out[(size_t)k * NN * 10 + (size_t)(Ig + r) * 10 + t], v);
            }
        }
        #pragma unroll
        for (int yy = 0; yy < 16; yy++) sT1[r][q + 4 * yy] = tval[yy];
    }

    if (!diag) {
        float tval[16];
        #pragma unroll
        for (int yy = 0; yy < 16; yy++) tval[yy] = 0.f;
        #pragma unroll
        for (int k = 0; k < 3; k++) {
            const float* rowp = Aks[k] + (size_t)(Jg + r) * NN + Ig + q;
            float wk = wk3[k];
            float ft[10];
            #pragma unroll
            for (int t = 0; t < 10; t++) ft[t] = 0.f;
            #pragma unroll
            for (int yy = 0; yy < 16; yy++) {
                int y = q + 4 * yy;
                float a = rowp[4 * yy];
                tval[yy] += wk * a;
                #pragma unroll
                for (int t = 0; t < 10; t++) ft[t] += a * tokI[k][y][t];
            }
            #pragma unroll
            for (int t = 0; t < 10; t++) {
                float v = ft[t];
                v += __shfl_down_sync(0xffffffffu, v, 2, 4);
                v += __shfl_down_sync(0xffffffffu, v, 1, 4);
                if (q == 0)
                    atomicAdd(&feat_out[(size_t)k * NN * 10 + (size_t)(Jg + r) * 10 + t], v);
            }
        }
        #pragma unroll
        for (int yy = 0; yy < 16; yy++) sT2[r][q + 4 * yy] = tval[yy];
    }
    __syncthreads();

    int y = tid & 63, xb = tid >> 6;
    if (diag) {
        #pragma unroll
        for (int i = 0; i < 16; i++) {
            int x = xb + 4 * i;
            g_adj[(size_t)(Ig + x) * NN + Jg + y] = sT1[x][y] + sT1[y][x];
        }
    } else {
        #pragma unroll
        for (int i = 0; i < 16; i++) {
            int x = xb + 4 * i;
            g_adj[(size_t)(Ig + x) * NN + Jg + y] = sT1[x][y] + sT2[y][x];
            g_adj[(size_t)(Jg + x) * NN + Ig + y] = sT2[x][y] + sT1[y][x];
        }
    }
}

// ---------------- tf32 tensor-core GEMM (big GEMMs) -------------------------
// C[M x 128] = A[M x K] @ B[K x 128], optional +bias, optional 0.5*(C+comb).
// CTA tile 64(M) x 128(N), BK=16, 256 threads = 8 warps (2M x 4N).
// Warp tile 32x32 via mma.sync.m16n8k8.tf32. Grid: (M/64, 1).
#define SAW 20    // A smem row stride (words): bank (20r+c)%32 bijective
#define SBW 136   // B smem row stride (words): bank (8k+n)%32 bijective

__device__ __forceinline__ unsigned f2tf(float x) {
    unsigned r;
    asm("cvt.rna.tf32.f32 %0, %1;" : "=r"(r) : "f"(x));
    return r;
}

__device__ __forceinline__ void mma8(float* c, const unsigned* a, const unsigned* b) {
    asm volatile(
        "mma.sync.aligned.m16n8k8.row.col.f32.tf32.tf32.f32 "
        "{%0,%1,%2,%3}, {%4,%5,%6,%7}, {%8,%9}, {%0,%1,%2,%3};"
        : "+f"(c[0]), "+f"(c[1]), "+f"(c[2]), "+f"(c[3])
        : "r"(a[0]), "r"(a[1]), "r"(a[2]), "r"(a[3]), "r"(b[0]), "r"(b[1]));
}

__global__ __launch_bounds__(256) void k_gemm_tc(
    const float* __restrict__ A, int lda, int K,
    const float* __restrict__ B,
    const float* __restrict__ bias,
    const float* __restrict__ comb,
    float* __restrict__ C)
{
    __shared__ unsigned sA[2][64 * SAW];   // [buf][m][k]
    __shared__ unsigned sB[2][16 * SBW];   // [buf][k][n]

    int t = threadIdx.x;
    int lane = t & 31, warp = t >> 5;
    int wm = (warp >> 2) * 32;       // 0,32
    int wn = (warp & 3) * 32;        // 0,32,64,96
    int rowBase = blockIdx.x * 64;

    // staging maps (coalesced global loads)
    int ar  = t >> 2;                // 0..63
    int ac4 = (t & 3) << 2;          // 0,4,8,12
    int bk_ = t >> 5;                // 0..7 (i=1 adds 8)
    int bc4 = (t & 31) << 2;         // 0..124

    float acc[2][4][4];
    #pragma unroll
    for (int ms = 0; ms < 2; ms++)
        #pragma unroll
        for (int ns = 0; ns < 4; ns++)
            #pragma unroll
            for (int j = 0; j < 4; j++) acc[ms][ns][j] = 0.f;

    float4 ra, rb0, rb1;

    // preload stage 0
    ra  = *(const float4*)(A + (size_t)(rowBase + ar) * lda + ac4);
    rb0 = *(const float4*)(B + (size_t)bk_ * 128 + bc4);
    rb1 = *(const float4*)(B + (size_t)(bk_ + 8) * 128 + bc4);
    {
        uint4 va = make_uint4(f2tf(ra.x), f2tf(ra.y), f2tf(ra.z), f2tf(ra.w));
        *(uint4*)&sA[0][ar * SAW + ac4] = va;
        uint4 v0 = make_uint4(f2tf(rb0.x), f2tf(rb0.y), f2tf(rb0.z), f2tf(rb0.w));
        uint4 v1 = make_uint4(f2tf(rb1.x), f2tf(rb1.y), f2tf(rb1.z), f2tf(rb1.w));
        *(uint4*)&sB[0][bk_ * SBW + bc4]       = v0;
        *(uint4*)&sB[0][(bk_ + 8) * SBW + bc4] = v1;
    }
    __syncthreads();

    int cur = 0;
    int nStages = K / 16;
    for (int s = 0; s < nStages; s++) {
        bool hn = (s + 1 < nStages);
        if (hn) {
            int k0n = (s + 1) * 16;
            ra  = *(const float4*)(A + (size_t)(rowBase + ar) * lda + k0n + ac4);
            rb0 = *(const float4*)(B + (size_t)(k0n + bk_) * 128 + bc4);
            rb1 = *(const float4*)(B + (size_t)(k0n + bk_ + 8) * 128 + bc4);
        }

        #pragma unroll
        for (int k8 = 0; k8 < 16; k8 += 8) {
            unsigned afr[2][4];
            #pragma unroll
            for (int ms = 0; ms < 2; ms++) {
                int r0 = wm + ms * 16 + (lane >> 2);
                int kc = k8 + (lane & 3);
                afr[ms][0] = sA[cur][r0 * SAW + kc];
                afr[ms][1] = sA[cur][(r0 + 8) * SAW + kc];
                afr[ms][2] = sA[cur][r0 * SAW + kc + 4];
                afr[ms][3] = sA[cur][(r0 + 8) * SAW + kc + 4];
            }
            unsigned bfr[4][2];
            #pragma unroll
            for (int ns = 0; ns < 4; ns++) {
                int n0 = wn + ns * 8 + (lane >> 2);
                int kc = k8 + (lane & 3);
                bfr[ns][0] = sB[cur][kc * SBW + n0];
                bfr[ns][1] = sB[cur][(kc + 4) * SBW + n0];
            }
            #pragma unroll
            for (int ms = 0; ms < 2; ms++)
                #pragma unroll
                for (int ns = 0; ns < 4; ns++)
                    mma8(acc[ms][ns], afr[ms], bfr[ns]);
        }

        if (hn) {
            int nxt = cur ^ 1;
            uint4 va = make_uint4(f2tf(ra.x), f2tf(ra.y), f2tf(ra.z), f2tf(ra.w));
            *(uint4*)&sA[nxt][ar * SAW + ac4] = va;
            uint4 v0 = make_uint4(f2tf(rb0.x), f2tf(rb0.y), f2tf(rb0.z), f2tf(rb0.w));
            uint4 v1 = make_uint4(f2tf(rb1.x), f2tf(rb1.y), f2tf(rb1.z), f2tf(rb1.w));
            *(uint4*)&sB[nxt][bk_ * SBW + bc4]       = v0;
            *(uint4*)&sB[nxt][(bk_ + 8) * SBW + bc4] = v1;
            __syncthreads();
            cur = nxt;
        }
    }

    // ---- epilogue: c0,c1 -> (row,col..col+1); c2,c3 -> (row+8, ...) ----
    #pragma unroll
    for (int ms = 0; ms < 2; ms++) {
        int rbase = rowBase + wm + ms * 16 + (lane >> 2);
        #pragma unroll
        for (int ns = 0; ns < 4; ns++) {
            int col = wn + ns * 8 + 2 * (lane & 3);
            #pragma unroll
            for (int h = 0; h < 2; h++) {
                int row = rbase + 8 * h;
                float x0 = acc[ms][ns][2 * h];
                float x1 = acc[ms][ns][2 * h + 1];
                if (bias) { x0 += bias[col]; x1 += bias[col + 1]; }
                if (comb) {
                    const float* cp = comb + (size_t)row * 128 + col;
                    x0 = 0.5f * (x0 + cp[0]);
                    x1 = 0.5f * (x1 + cp[1]);
                }
                *(float2*)(C + (size_t)row * 128 + col) = make_float2(x0, x1);
            }
        }
    }
}

// ---------------- fp32 SIMT GEMM for the small multiplies (unchanged) -------
__device__ __forceinline__ void gemm_body(
    const float* __restrict__ A, int lda, int K,
    const float* __restrict__ B,
    const float* __restrict__ bias,
    const float* __restrict__ comb,
    float* __restrict__ C)
{
    __shared__ float sA[2][16][68];
    __shared__ float sB[2][16][68];

    int t = threadIdx.x;
    int rowBase = blockIdx.x * 64;
    int cBase   = blockIdx.y * 64;

    float acc[4][4];
    #pragma unroll
    for (int i = 0; i < 4; i++)
        #pragma unroll
        for (int j = 0; j < 4; j++) acc[i][j] = 0.f;

    int a_row = t >> 2;
    int a_k4  = (t & 3) * 4;
    int b_k  = t >> 4;
    int b_n4 = (t & 15) * 4;
    int tm = (t & 15) * 4;
    int tn = (t >> 4) * 4;

    float4 ra, rb;
    ra = *(const float4*)(A + (size_t)(rowBase + a_row) * lda + a_k4);
    rb = *(const float4*)(B + (size_t)b_k * 128 + cBase + b_n4);
    {
        float aa[4] = {ra.x, ra.y, ra.z, ra.w};
        #pragma unroll
        for (int c = 0; c < 4; c++) sA[0][a_k4 + c][a_row] = aa[c];
        *(float4*)&sB[0][b_k][b_n4] = rb;
    }
    __syncthreads();

    int cur = 0;
    for (int k0 = 0; k0 < K; k0 += 16) {
        bool has_next = (k0 + 16 < K);
        if (has_next) {
            ra = *(const float4*)(A + (size_t)(rowBase + a_row) * lda + k0 + 16 + a_k4);
            rb = *(const float4*)(B + (size_t)(k0 + 16 + b_k) * 128 + cBase + b_n4);
        }
        #pragma unroll
        for (int kk = 0; kk < 16; kk++) {
            float4 av = *(const float4*)&sA[cur][kk][tm];
            float4 bv = *(const float4*)&sB[cur][kk][tn];
            float a4[4] = {av.x, av.y, av.z, av.w};
            float b4[4] = {bv.x, bv.y, bv.z, bv.w};
            #pragma unroll
            for (int i = 0; i < 4; i++)
                #pragma unroll
                for (int j = 0; j < 4; j++)
                    acc[i][j] += a4[i] * b4[j];
        }
        if (has_next) {
            int nxt = cur ^ 1;
            float aa[4] = {ra.x, ra.y, ra.z, ra.w};
            #pragma unroll
            for (int c = 0; c < 4; c++) sA[nxt][a_k4 + c][a_row] = aa[c];
            *(float4*)&sB[nxt][b_k][b_n4] = rb;
            __syncthreads();
            cur = nxt;
        }
    }

    #pragma unroll
    for (int i = 0; i < 4; i++) {
        int row = rowBase + tm + i;
        int col0 = cBase + tn;
        float vv[4];
        #pragma unroll
        for (int j = 0; j < 4; j++) {
            float x = acc[i][j];
            if (bias) x += bias[col0 + j];
            if (comb) x = 0.5f * (x + comb[(size_t)row * 128 + col0 + j]);
            vv[j] = x;
        }
        *(float4*)(C + (size_t)row * 128 + col0) = make_float4(vv[0], vv[1], vv[2], vv[3]);
    }
}

__global__ __launch_bounds__(256) void k_gemm_h1(const float* __restrict__ f,
                                                 const float* __restrict__ W1) {
    gemm_body(f, 256, 256, W1, nullptr, nullptr, g_H1);
}
__global__ __launch_bounds__(256) void k_gemm_h2(const float* __restrict__ W2) {
    gemm_body(g_U1, 128, 128, W2, nullptr, nullptr, g_H2);
}
__global__ __launch_bounds__(256) void k_gemm_u1_tc(const float* __restrict__ b1) {
    // forwarding wrappers keep __device__ globals out of host code
}

// ---------------- launch ----------------------------------------------------
__global__ __launch_bounds__(256) void k_u1(const float* __restrict__ b1);
__global__ __launch_bounds__(256) void k_u2(const float* __restrict__ b2, float* __restrict__ out);

__global__ __launch_bounds__(256) void k_u1(const float* __restrict__ b1) {
    k_gemm_tc_body: ;
}

extern "C" void kernel_launch(void* const* d_in, const int* in_sizes, int n_in,
                              void* d_out, int out_size) {
    const float* feature = (const float*)d_in[0];
    const float* A1 = (const float*)d_in[1];
    const float* A2 = (const float*)d_in[2];
    const float* A3 = (const float*)d_in[3];
    const float* T1 = (const float*)d_in[4];
    const float* T2 = (const float*)d_in[5];
    const float* T3 = (const float*)d_in[6];
    const float* wb = (const float*)d_in[7];
    const float* W1 = (const float*)d_in[8];
    const float* b1 = (const float*)d_in[9];
    const float* W2 = (const float*)d_in[10];
    const float* b2 = (const float*)d_in[11];

    float* out = (float*)d_out;
    float* feat_out = out + (size_t)NN * NOUT;

    int nfeat = 3 * NN * 10;
    k_zero<<<(nfeat + 255) / 256, 256>>>(feat_out, nfeat);

    dim3 gb(128, 128);
    k_build<<<gb, 256>>>(A1, A2, A3, T1, T2, T3, wb, feat_out);

    dim3 gg(128, 2);
    k_gemm_h1<<<gg, 256>>>(feature, W1);

    // big GEMMs on tensor cores: need device-global pointers; obtain via
    // cudaGetSymbolAddress-free path: pass through kernel params using the
    // device symbols directly in a launch wrapper is not possible from host,
    // so use cudaMemcpyFromSymbolAsync-free approach: launch with symbol
    // addresses resolved at module load via a helper kernel is overkill —
    // instead k_gemm_tc takes raw pointers; resolve them with
    // cudaGetSymbolAddress once per launch (allowed: no alloc, no sync).
    static float* p_adj = nullptr;
    static float* p_H1 = nullptr;
    static float* p_U1 = nullptr;
    static float* p_H2 = nullptr;
    if (!p_adj) {
        cudaGetSymbolAddress((void**)&p_adj, g_adj);
        cudaGetSymbolAddress((void**)&p_H1, g_H1);
        cudaGetSymbolAddress((void**)&p_U1, g_U1);
        cudaGetSymbolAddress((void**)&p_H2, g_H2);
    }

    k_gemm_tc<<<128, 256>>>(p_adj, NN, NN, p_H1, b1, nullptr, p_U1);
    k_gemm_h2<<<gg, 256>>>(W2);
    k_gemm_tc<<<128, 256>>>(p_adj, NN, NN, p_H2, b2, p_U1, out);
}

// round 16
// speedup vs baseline: 3.2926x; 1.3103x over previous
#include <cuda_runtime.h>
#include <cuda_bf16.h>
#include <cstddef>
#include <cstdint>

#define NN   8192
#define TS   64
#define NOUT 128

// ---------------- scratch (device globals: no allocation allowed) ----------
__device__ float g_adj[(size_t)NN * NN];     // 256 MB, tf32-rounded values
__device__ float g_H1[(size_t)NN * NOUT];    // tf32-rounded
__device__ float g_U1[(size_t)NN * NOUT];    // fp32
__device__ float g_H2[(size_t)NN * NOUT];    // tf32-rounded

// ---------------- tf32 helpers ----------------------------------------------
__device__ __forceinline__ unsigned f2tf(float x) {
    unsigned r;
    asm("cvt.rna.tf32.f32 %0, %1;" : "=r"(r) : "f"(x));
    return r;
}
__device__ __forceinline__ float f2tf_f(float x) { return __uint_as_float(f2tf(x)); }

// ---------------- zero kernel ----------------------------------------------
__global__ void k_zero(float* __restrict__ p, int n) {
    int i = blockIdx.x * 256 + threadIdx.x;
    if (i < n) p[i] = 0.f;
}

// ---------------- pass 1: adj build + fused A@token -------------------------
// Unchanged except: adj values are tf32-rounded (rna) at store time, so the
// tensor-core GEMMs can consume raw bits with exact rna semantics.
__global__ __launch_bounds__(256) void k_build(
    const float* __restrict__ A1, const float* __restrict__ A2, const float* __restrict__ A3,
    const float* __restrict__ T1, const float* __restrict__ T2, const float* __restrict__ T3,
    const float* __restrict__ wb, float* __restrict__ feat_out)
{
    int I = blockIdx.y, J = blockIdx.x;
    if (J < I) return;

    __shared__ float sT1[TS][TS + 1];
    __shared__ float sT2[TS][TS + 1];
    __shared__ float tokJ[3][TS][10];
    __shared__ float tokI[3][TS][10];

    int tid = threadIdx.x;
    int Ig = I * TS, Jg = J * TS;
    const float* Aks[3] = {A1, A2, A3};
    const float* Tks[3] = {T1, T2, T3};
    float wk3[3] = {wb[0], wb[1], wb[2]};

    for (int idx = tid; idx < 3 * TS * 10; idx += 256) {
        int k = idx / (TS * 10);
        int rem = idx % (TS * 10);
        int row = rem / 10, t = rem % 10;
        tokJ[k][row][t] = Tks[k][(Jg + row) * 10 + t];
        tokI[k][row][t] = Tks[k][(Ig + row) * 10 + t];
    }
    __syncthreads();

    int r = tid >> 2;
    int q = tid & 3;
    bool diag = (I == J);

    {
        float tval[16];
        #pragma unroll
        for (int yy = 0; yy < 16; yy++) tval[yy] = 0.f;
        #pragma unroll
        for (int k = 0; k < 3; k++) {
            const float* rowp = Aks[k] + (size_t)(Ig + r) * NN + Jg + q;
            float wk = wk3[k];
            float ft[10];
            #pragma unroll
            for (int t = 0; t < 10; t++) ft[t] = 0.f;
            #pragma unroll
            for (int yy = 0; yy < 16; yy++) {
                int y = q + 4 * yy;
                float a = rowp[4 * yy];
                tval[yy] += wk * a;
                #pragma unroll
                for (int t = 0; t < 10; t++) ft[t] += a * tokJ[k][y][t];
            }
            #pragma unroll
            for (int t = 0; t < 10; t++) {
                float v = ft[t];
                v += __shfl_down_sync(0xffffffffu, v, 2, 4);
                v += __shfl_down_sync(0xffffffffu, v, 1, 4);
                if (q == 0)
                    atomicAdd(&feat_out[(size_t)k * NN * 10 + (size_t)(Ig + r) * 10 + t], v);
            }
        }
        #pragma unroll
        for (int yy = 0; yy < 16; yy++) sT1[r][q + 4 * yy] = tval[yy];
    }

    if (!diag) {
        float tval[16];
        #pragma unroll
        for (int yy = 0; yy < 16; yy++) tval[yy] = 0.f;
        #pragma unroll
        for (int k = 0; k < 3; k++) {
            const float* rowp = Aks[k] + (size_t)(Jg + r) * NN + Ig + q;
            float wk = wk3[k];
            float ft[10];
            #pragma unroll
            for (int t = 0; t < 10; t++) ft[t] = 0.f;
            #pragma unroll
            for (int yy = 0; yy < 16; yy++) {
                int y = q + 4 * yy;
                float a = rowp[4 * yy];
                tval[yy] += wk * a;
                #pragma unroll
                for (int t = 0; t < 10; t++) ft[t] += a * tokI[k][y][t];
            }
            #pragma unroll
            for (int t = 0; t < 10; t++) {
                float v = ft[t];
                v += __shfl_down_sync(0xffffffffu, v, 2, 4);
                v += __shfl_down_sync(0xffffffffu, v, 1, 4);
                if (q == 0)
                    atomicAdd(&feat_out[(size_t)k * NN * 10 + (size_t)(Jg + r) * 10 + t], v);
            }
        }
        #pragma unroll
        for (int yy = 0; yy < 16; yy++) sT2[r][q + 4 * yy] = tval[yy];
    }
    __syncthreads();

    int y = tid & 63, xb = tid >> 6;
    if (diag) {
        #pragma unroll
        for (int i = 0; i < 16; i++) {
            int x = xb + 4 * i;
            g_adj[(size_t)(Ig + x) * NN + Jg + y] = f2tf_f(sT1[x][y] + sT1[y][x]);
        }
    } else {
        #pragma unroll
        for (int i = 0; i < 16; i++) {
            int x = xb + 4 * i;
            g_adj[(size_t)(Ig + x) * NN + Jg + y] = f2tf_f(sT1[x][y] + sT2[y][x]);
            g_adj[(size_t)(Jg + x) * NN + Ig + y] = f2tf_f(sT2[x][y] + sT1[y][x]);
        }
    }
}

// ---------------- tf32 tensor-core GEMM with cp.async pipeline --------------
// C[M x 128] = A[M x K] @ B[K x 128]; CTA tile 64(M) x 64(N), BK=16,
// grid (M/64, 2), 256 threads = 8 warps (2M x 4N), warp tile 32x16.
// 4-stage cp.async pipeline; operands are pre-rounded tf32 (raw-bit feed).
#define SAW 20                 // A smem row stride (words): (20m+k)%32 conflict-free
#define SBW 72                 // B smem row stride (words): (8k+n)%32 conflict-free
#define ASTG (64 * SAW)
#define BSTG (16 * SBW)

__device__ __forceinline__ void cp16(uint32_t dst, const void* src) {
    asm volatile("cp.async.cg.shared.global [%0], [%1], 16;" :: "r"(dst), "l"(src));
}
#define CP_COMMIT() asm volatile("cp.async.commit_group;")
#define CP_WAIT2()  asm volatile("cp.async.wait_group 2;")

__device__ __forceinline__ void mma8(float* c, const unsigned* a, const unsigned* b) {
    asm volatile(
        "mma.sync.aligned.m16n8k8.row.col.f32.tf32.tf32.f32 "
        "{%0,%1,%2,%3}, {%4,%5,%6,%7}, {%8,%9}, {%0,%1,%2,%3};"
        : "+f"(c[0]), "+f"(c[1]), "+f"(c[2]), "+f"(c[3])
        : "r"(a[0]), "r"(a[1]), "r"(a[2]), "r"(a[3]), "r"(b[0]), "r"(b[1]));
}

__global__ __launch_bounds__(256) void k_gemm_tc(
    const float* __restrict__ A, int lda, int K,
    const float* __restrict__ B,
    const float* __restrict__ bias,
    const float* __restrict__ comb,
    float* __restrict__ C)
{
    __shared__ float sA[4 * ASTG];   // 20.0 KB
    __shared__ float sB[4 * BSTG];   // 18.0 KB

    int t = threadIdx.x;
    int lane = t & 31, warp = t >> 5;
    int wm = (warp >> 2) * 32;       // 0,32
    int wn = (warp & 3) * 16;        // 0,16,32,48
    int rowBase = blockIdx.x * 64;
    int cBase   = blockIdx.y * 64;

    // cp.async staging maps (coalesced, 16B granules)
    int ar  = t >> 2;                // 0..63
    int ac4 = (t & 3) << 2;          // 0,4,8,12
    int bk  = t >> 4;                // 0..15
    int bn4 = (t & 15) << 2;         // 0..60

    uint32_t saA = (uint32_t)__cvta_generic_to_shared(sA);
    uint32_t saB = (uint32_t)__cvta_generic_to_shared(sB);
    uint32_t dstA = saA + (uint32_t)(ar * SAW + ac4) * 4;
    uint32_t dstB = saB + (uint32_t)(bk * SBW + bn4) * 4;
    const float* agp = A + (size_t)(rowBase + ar) * lda + ac4;
    const float* bgp = B + (size_t)bk * 128 + cBase + bn4;

    float acc[2][2][4];
    #pragma unroll
    for (int ms = 0; ms < 2; ms++)
        #pragma unroll
        for (int ns = 0; ns < 2; ns++)
            #pragma unroll
            for (int j = 0; j < 4; j++) acc[ms][ns][j] = 0.f;

    int nStages = K / 16;

    // prologue: stages 0,1,2
    #pragma unroll
    for (int s = 0; s < 3; s++) {
        cp16(dstA + (uint32_t)(s * ASTG) * 4, agp + s * 16);
        cp16(dstB + (uint32_t)(s * BSTG) * 4, bgp + (size_t)s * 16 * 128);
        CP_COMMIT();
    }

    for (int s = 0; s < nStages; s++) {
        CP_WAIT2();
        __syncthreads();

        if (s + 3 < nStages) {
            int buf = (s + 3) & 3;
            cp16(dstA + (uint32_t)(buf * ASTG) * 4, agp + (s + 3) * 16);
            cp16(dstB + (uint32_t)(buf * BSTG) * 4, bgp + (size_t)(s + 3) * 16 * 128);
        }
        CP_COMMIT();   // empty groups near the tail keep wait-count semantics

        const float* fA = sA + (s & 3) * ASTG;
        const float* fB = sB + (s & 3) * BSTG;

        #pragma unroll
        for (int k8 = 0; k8 < 16; k8 += 8) {
            int kc = k8 + (lane & 3);
            unsigned afr[2][4];
            #pragma unroll
            for (int ms = 0; ms < 2; ms++) {
                int r0 = wm + ms * 16 + (lane >> 2);
                afr[ms][0] = __float_as_uint(fA[r0 * SAW + kc]);
                afr[ms][1] = __float_as_uint(fA[(r0 + 8) * SAW + kc]);
                afr[ms][2] = __float_as_uint(fA[r0 * SAW + kc + 4]);
                afr[ms][3] = __float_as_uint(fA[(r0 + 8) * SAW + kc + 4]);
            }
            unsigned bfr[2][2];
            #pragma unroll
            for (int ns = 0; ns < 2; ns++) {
                int n0 = wn + ns * 8 + (lane >> 2);
                bfr[ns][0] = __float_as_uint(fB[kc * SBW + n0]);
                bfr[ns][1] = __float_as_uint(fB[(kc + 4) * SBW + n0]);
            }
            #pragma unroll
            for (int ms = 0; ms < 2; ms++)
                #pragma unroll
                for (int ns = 0; ns < 2; ns++)
                    mma8(acc[ms][ns], afr[ms], bfr[ns]);
        }
    }

    // ---- epilogue ----
    #pragma unroll
    for (int ms = 0; ms < 2; ms++) {
        int rbase = rowBase + wm + ms * 16 + (lane >> 2);
        #pragma unroll
        for (int ns = 0; ns < 2; ns++) {
            int col = cBase + wn + ns * 8 + 2 * (lane & 3);
            #pragma unroll
            for (int h = 0; h < 2; h++) {
                int row = rbase + 8 * h;
                float x0 = acc[ms][ns][2 * h];
                float x1 = acc[ms][ns][2 * h + 1];
                if (bias) { x0 += bias[col]; x1 += bias[col + 1]; }
                if (comb) {
                    const float* cp = comb + (size_t)row * 128 + col;
                    x0 = 0.5f * (x0 + cp[0]);
                    x1 = 0.5f * (x1 + cp[1]);
                }
                *(float2*)(C + (size_t)row * 128 + col) = make_float2(x0, x1);
            }
        }
    }
}

// ---------------- fp32 SIMT GEMM for the small multiplies -------------------
// round_out: store tf32-rounded values (producers feeding the tc GEMMs).
__device__ __forceinline__ void gemm_body(
    const float* __restrict__ A, int lda, int K,
    const float* __restrict__ B,
    float* __restrict__ C, bool round_out)
{
    __shared__ float sA[2][16][68];
    __shared__ float sB[2][16][68];

    int t = threadIdx.x;
    int rowBase = blockIdx.x * 64;
    int cBase   = blockIdx.y * 64;

    float acc[4][4];
    #pragma unroll
    for (int i = 0; i < 4; i++)
        #pragma unroll
        for (int j = 0; j < 4; j++) acc[i][j] = 0.f;

    int a_row = t >> 2;
    int a_k4  = (t & 3) * 4;
    int b_k  = t >> 4;
    int b_n4 = (t & 15) * 4;
    int tm = (t & 15) * 4;
    int tn = (t >> 4) * 4;

    float4 ra, rb;
    ra = *(const float4*)(A + (size_t)(rowBase + a_row) * lda + a_k4);
    rb = *(const float4*)(B + (size_t)b_k * 128 + cBase + b_n4);
    {
        float aa[4] = {ra.x, ra.y, ra.z, ra.w};
        #pragma unroll
        for (int c = 0; c < 4; c++) sA[0][a_k4 + c][a_row] = aa[c];
        *(float4*)&sB[0][b_k][b_n4] = rb;
    }
    __syncthreads();

    int cur = 0;
    for (int k0 = 0; k0 < K; k0 += 16) {
        bool has_next = (k0 + 16 < K);
        if (has_next) {
            ra = *(const float4*)(A + (size_t)(rowBase + a_row) * lda + k0 + 16 + a_k4);
            rb = *(const float4*)(B + (size_t)(k0 + 16 + b_k) * 128 + cBase + b_n4);
        }
        #pragma unroll
        for (int kk = 0; kk < 16; kk++) {
            float4 av = *(const float4*)&sA[cur][kk][tm];
            float4 bv = *(const float4*)&sB[cur][kk][tn];
            float a4[4] = {av.x, av.y, av.z, av.w};
            float b4[4] = {bv.x, bv.y, bv.z, bv.w};
            #pragma unroll
            for (int i = 0; i < 4; i++)
                #pragma unroll
                for (int j = 0; j < 4; j++)
                    acc[i][j] += a4[i] * b4[j];
        }
        if (has_next) {
            int nxt = cur ^ 1;
            float aa[4] = {ra.x, ra.y, ra.z, ra.w};
            #pragma unroll
            for (int c = 0; c < 4; c++) sA[nxt][a_k4 + c][a_row] = aa[c];
            *(float4*)&sB[nxt][b_k][b_n4] = rb;
            __syncthreads();
            cur = nxt;
        }
    }

    #pragma unroll
    for (int i = 0; i < 4; i++) {
        int row = rowBase + tm + i;
        int col0 = cBase + tn;
        float vv[4];
        #pragma unroll
        for (int j = 0; j < 4; j++) {
            float x = acc[i][j];
            vv[j] = round_out ? f2tf_f(x) : x;
        }
        *(float4*)(C + (size_t)row * 128 + col0) = make_float4(vv[0], vv[1], vv[2], vv[3]);
    }
}

__global__ __launch_bounds__(256) void k_gemm_h1(const float* __restrict__ f,
                                                 const float* __restrict__ W1) {
    gemm_body(f, 256, 256, W1, g_H1, true);
}
__global__ __launch_bounds__(256) void k_gemm_h2(const float* __restrict__ W2) {
    gemm_body(g_U1, 128, 128, W2, g_H2, true);
}

// ---------------- launch ----------------------------------------------------
extern "C" void kernel_launch(void* const* d_in, const int* in_sizes, int n_in,
                              void* d_out, int out_size) {
    const float* feature = (const float*)d_in[0];
    const float* A1 = (const float*)d_in[1];
    const float* A2 = (const float*)d_in[2];
    const float* A3 = (const float*)d_in[3];
    const float* T1 = (const float*)d_in[4];
    const float* T2 = (const float*)d_in[5];
    const float* T3 = (const float*)d_in[6];
    const float* wb = (const float*)d_in[7];
    const float* W1 = (const float*)d_in[8];
    const float* b1 = (const float*)d_in[9];
    const float* W2 = (const float*)d_in[10];
    const float* b2 = (const float*)d_in[11];

    float* out = (float*)d_out;
    float* feat_out = out + (size_t)NN * NOUT;

    int nfeat = 3 * NN * 10;
    k_zero<<<(nfeat + 255) / 256, 256>>>(feat_out, nfeat);

    dim3 gb(128, 128);
    k_build<<<gb, 256>>>(A1, A2, A3, T1, T2, T3, wb, feat_out);

    dim3 gg(128, 2);
    k_gemm_h1<<<gg, 256>>>(feature, W1);

    static float* p_adj = nullptr;
    static float* p_H1 = nullptr;
    static float* p_U1 = nullptr;
    static float* p_H2 = nullptr;
    if (!p_adj) {
        cudaGetSymbolAddress((void**)&p_adj, g_adj);
        cudaGetSymbolAddress((void**)&p_H1, g_H1);
        cudaGetSymbolAddress((void**)&p_U1, g_U1);
        cudaGetSymbolAddress((void**)&p_H2, g_H2);
    }

    dim3 gt(128, 2);
    k_gemm_tc<<<gt, 256>>>(p_adj, NN, NN, p_H1, b1, nullptr, p_U1);
    k_gemm_h2<<<gg, 256>>>(W2);
    k_gemm_tc<<<gt, 256>>>(p_adj, NN, NN, p_H2, b2, p_U1, out);
}